// round 1
// baseline (speedup 1.0000x reference)
#include <cuda_runtime.h>
#include <cuda_bf16.h>

// Problem shapes (fixed by the dataset)
#define M_DIM 4
#define N_DIM 64
#define B_DIM 256
#define C_DIM 512
#define H_DIM 64
#define EPSILON 0.1f

// ETA_FAULT table (12 x 4), exact values from the reference
__constant__ float c_fault[12][4] = {
    { 0.99997f, -1.0f,     0.0f,     9.1182e-18f},
    {-0.55856f, -1.0f,     0.0f,    -3.7472e-10f},
    {-16.919f,  14.562f,   0.086479f, 82.578f},
    { 1.0f,     -1.0f,     0.0f,     4.4982e-16f},
    { 1.6839f,  -2.2404f, -2.5173f,  1.1147f},
    {-0.55856f, -1.0f,     0.0f,    -3.7472e-10f},
    { 0.99997f, -1.0f,     0.0f,     9.1182e-18f},
    { 0.23198f, -0.78334f,-0.41194f, 3.4699f},
    { 1.0f,     -1.0f,     0.0f,     4.4982e-16f},
    { 0.99997f, -1.0f,     0.0f,     9.1182e-18f},
    {-0.24548f, -0.02379f, 0.81499f, 1.5337f},
    {-1.0f,     -1.0f,     0.0f,     4.407e-16f},
};

// eta[n][k] scratch, recomputed every launch (deterministic, graph-safe)
__device__ float g_eta[N_DIM * 4];

__device__ __forceinline__ float sigmoidf_dev(float x) {
    return 1.0f / (1.0f + __expf(-x));
}

// tanh(x) = 1 - 2/(exp(2x)+1).  Exact saturation at +/-1, exact 0 at 0.
// abs error ~1e-7 (ex2.approx + rcp.approx), ~6 instrs incl. 2 MUFU.
__device__ __forceinline__ float fast_tanh(float x) {
    float e = __expf(2.0f * x);
    return 1.0f - __fdividef(2.0f, e + 1.0f);
}

// ---------------------------------------------------------------------------
// Kernel 1: compute eta[64][4] (tiny MLP).  One block, 64 threads, 1 row each.
// ---------------------------------------------------------------------------
__global__ void eta_kernel(const float* __restrict__ rt,
                           const float* __restrict__ noise,
                           const float* __restrict__ Xmax,
                           const float* __restrict__ Xmin,
                           const float* __restrict__ Ymax,
                           const float* __restrict__ Ymin,
                           const float* __restrict__ W1,
                           const float* __restrict__ b1,
                           const float* __restrict__ W2,
                           const float* __restrict__ b2) {
    int n = threadIdx.x;
    if (n >= N_DIM) return;

    // RT[i] for i in 0..5 (entries 6..8 of RTn are zero and only the first 6
    // plus their ratios feed ext)
    float RTv[6];
    #pragma unroll
    for (int i = 0; i < 6; i++) {
        float rtn = sigmoidf_dev(rt[i]);
        float RT  = rtn * (Xmax[i] - Xmin[i]) + Xmin[i];
        float nf  = (noise[n * 9 + i] * 2.0f - 1.0f) * EPSILON + 1.0f;
        RTv[i]    = RT * nf;
    }
    float ext[9];
    ext[0] = RTv[0]; ext[1] = RTv[1]; ext[2] = RTv[2];
    ext[3] = RTv[3]; ext[4] = RTv[4]; ext[5] = RTv[5];
    ext[6] = RTv[1] / RTv[0];
    ext[7] = RTv[3] / RTv[2];
    ext[8] = RTv[5] / RTv[4];

    float xn[9];
    #pragma unroll
    for (int i = 0; i < 9; i++)
        xn[i] = (ext[i] - Xmin[i]) / (Xmax[i] - Xmin[i]);

    // hidden layer: h = relu(xn @ W1 + b1), W1 is [9, 64] row-major
    float h[H_DIM];
    #pragma unroll 8
    for (int j = 0; j < H_DIM; j++) {
        float s = b1[j];
        #pragma unroll
        for (int i = 0; i < 9; i++)
            s = fmaf(xn[i], W1[i * H_DIM + j], s);
        h[j] = fmaxf(s, 0.0f);
    }

    // output layer: eta = sigmoid(h @ W2 + b2) * (Ymax - Ymin) + Ymin
    #pragma unroll
    for (int k = 0; k < 4; k++) {
        float s = b2[k];
        #pragma unroll 16
        for (int j = 0; j < H_DIM; j++)
            s = fmaf(h[j], W2[j * 4 + k], s);
        g_eta[n * 4 + k] = sigmoidf_dev(s) * (Ymax[k] - Ymin[k]) + Ymin[k];
    }
}

// ---------------------------------------------------------------------------
// Kernel 2: elementwise map.  Each thread owns (m, n, c4) = 4 consecutive c
// values and iterates over a 32-wide chunk of the b dimension.  Params live
// in registers for the whole loop; loads/stores are 512B-contiguous per warp.
// ---------------------------------------------------------------------------
#define BCHUNK 32
#define NCHUNKS (B_DIM / BCHUNK)   // 8
#define C4 (C_DIM / 4)             // 128

__global__ __launch_bounds__(256) void tanhrt_kernel(
        const float4* __restrict__ z,
        const int*    __restrict__ mask,
        float4*       __restrict__ out) {
    int tid = blockIdx.x * blockDim.x + threadIdx.x;
    int c4    =  tid         & (C4 - 1);      // 0..127
    int n     = (tid >> 7)   & (N_DIM - 1);   // 0..63
    int m     = (tid >> 13)  & (M_DIM - 1);   // 0..3
    int chunk =  tid >> 15;                   // 0..7

    // Gather the 4 parameter sets for this thread's 4 c-columns.
    float e0[4], e1[4], e2[4], e3[4];
    #pragma unroll
    for (int j = 0; j < 4; j++) {
        int c  = c4 * 4 + j;
        int mk = mask[m * C_DIM + c];
        const float* p = (mk == 0) ? (g_eta + n * 4) : &c_fault[mk - 1][0];
        e0[j] = p[0]; e1[j] = p[1]; e2[j] = p[2]; e3[j] = p[3];
    }

    // base index in float4 units: (((m*64+n)*256 + chunk*32) * 512 + c4*4)/4
    int base = ((m * N_DIM + n) * B_DIM + chunk * BCHUNK) * C4 + c4;

    #pragma unroll 4
    for (int b = 0; b < BCHUNK; b++) {
        int idx = base + b * C4;
        float4 v = z[idx];
        float4 r;
        r.x = fmaf(e1[0], fast_tanh((v.x - e2[0]) * e3[0]), e0[0]);
        r.y = fmaf(e1[1], fast_tanh((v.y - e2[1]) * e3[1]), e0[1]);
        r.z = fmaf(e1[2], fast_tanh((v.z - e2[2]) * e3[2]), e0[2]);
        r.w = fmaf(e1[3], fast_tanh((v.w - e2[3]) * e3[3]), e0[3]);
        out[idx] = r;
    }
}

// ---------------------------------------------------------------------------
// Launch
// ---------------------------------------------------------------------------
extern "C" void kernel_launch(void* const* d_in, const int* in_sizes, int n_in,
                              void* d_out, int out_size) {
    // metadata order: z, rt_, noise, X_max, X_min, Y_max, Y_min,
    //                 W1, b1, W2, b2, mask
    const float* z     = (const float*)d_in[0];
    const float* rt    = (const float*)d_in[1];
    const float* noise = (const float*)d_in[2];
    const float* Xmax  = (const float*)d_in[3];
    const float* Xmin  = (const float*)d_in[4];
    const float* Ymax  = (const float*)d_in[5];
    const float* Ymin  = (const float*)d_in[6];
    const float* W1    = (const float*)d_in[7];
    const float* b1    = (const float*)d_in[8];
    const float* W2    = (const float*)d_in[9];
    const float* b2    = (const float*)d_in[10];
    const int*   mask  = (const int*)  d_in[11];

    eta_kernel<<<1, N_DIM>>>(rt, noise, Xmax, Xmin, Ymax, Ymin,
                             W1, b1, W2, b2);

    int total_threads = NCHUNKS * M_DIM * N_DIM * C4;  // 262144
    tanhrt_kernel<<<total_threads / 256, 256>>>(
        (const float4*)z, mask, (float4*)d_out);
}

// round 3
// speedup vs baseline: 1.2164x; 1.2164x over previous
#include <cuda_runtime.h>
#include <cuda_bf16.h>

#define M_DIM 4
#define N_DIM 64
#define B_DIM 256
#define C_DIM 512
#define H_DIM 64
#define EPSILON 0.1f
#define BCHUNK 32
#define C4 (C_DIM / 4)     // 128

// ETA_FAULT table (12 x 4), exact values from the reference
__constant__ float c_fault[12][4] = {
    { 0.99997f, -1.0f,     0.0f,      9.1182e-18f},
    {-0.55856f, -1.0f,     0.0f,     -3.7472e-10f},
    {-16.919f,  14.562f,   0.086479f, 82.578f},
    { 1.0f,     -1.0f,     0.0f,      4.4982e-16f},
    { 1.6839f,  -2.2404f, -2.5173f,   1.1147f},
    {-0.55856f, -1.0f,     0.0f,     -3.7472e-10f},
    { 0.99997f, -1.0f,     0.0f,      9.1182e-18f},
    { 0.23198f, -0.78334f,-0.41194f,  3.4699f},
    { 1.0f,     -1.0f,     0.0f,      4.4982e-16f},
    { 0.99997f, -1.0f,     0.0f,      9.1182e-18f},
    {-0.24548f, -0.02379f, 0.81499f,  1.5337f},
    {-1.0f,     -1.0f,     0.0f,      4.407e-16f},
};

__device__ __forceinline__ float sigmoidf_dev(float x) {
    return 1.0f / (1.0f + __expf(-x));
}

// tanh(x) = 1 - 2/(exp(2x)+1). Exact saturation, exact 0 at 0, ~1e-7 abs err.
__device__ __forceinline__ float fast_tanh(float x) {
    float e = __expf(2.0f * x);
    return 1.0f - __fdividef(2.0f, e + 1.0f);
}

// ---------------------------------------------------------------------------
// One fused kernel. Each block = one (m, n, chunk): 32 b-rows x 512 c-cols.
// Prologue: block cooperatively computes eta[n][0..3] (tiny MLP) in ~400 cyc.
// Main loop: thread t owns c-columns [4t, 4t+3]; params in registers; loads
// and stores are 512B-contiguous per warp, streaming-hinted (no reuse).
// ---------------------------------------------------------------------------
__global__ __launch_bounds__(128) void fused_tanhrt_kernel(
        const float4* __restrict__ z,
        const int4*   __restrict__ mask4,
        float4*       __restrict__ out,
        const float*  __restrict__ rt,
        const float*  __restrict__ noise,
        const float*  __restrict__ Xmax,
        const float*  __restrict__ Xmin,
        const float*  __restrict__ Ymax,
        const float*  __restrict__ Ymin,
        const float*  __restrict__ W1,
        const float*  __restrict__ b1,
        const float*  __restrict__ W2,
        const float*  __restrict__ b2) {
    __shared__ float sh[H_DIM];   // hidden activations
    __shared__ float se[4];       // eta[n][0..3]

    const int bx    = blockIdx.x;
    const int n     =  bx       & (N_DIM - 1);
    const int m     = (bx >> 6) & (M_DIM - 1);
    const int chunk =  bx >> 8;            // 0..7
    const int t     = threadIdx.x;         // 0..127
    const int lane  = t & 31;
    const int w     = t >> 5;              // 0..3

    // ---- Prologue phase 1: hidden layer (threads 0..63, one unit each) ----
    if (t < H_DIM) {
        float v[9];
        #pragma unroll
        for (int i = 0; i < 6; i++) {
            float rtn = sigmoidf_dev(rt[i]);
            float RT  = rtn * (Xmax[i] - Xmin[i]) + Xmin[i];
            float nf  = (noise[n * 9 + i] * 2.0f - 1.0f) * EPSILON + 1.0f;
            v[i]      = RT * nf;                      // RTv[i]
        }
        v[6] = v[1] / v[0];
        v[7] = v[3] / v[2];
        v[8] = v[5] / v[4];
        float xn[9];
        #pragma unroll
        for (int i = 0; i < 9; i++)
            xn[i] = (v[i] - Xmin[i]) / (Xmax[i] - Xmin[i]);

        float s = b1[t];
        #pragma unroll
        for (int i = 0; i < 9; i++)
            s = fmaf(xn[i], W1[i * H_DIM + t], s);
        sh[t] = fmaxf(s, 0.0f);
    }
    __syncthreads();

    // ---- Prologue phase 2: output layer (warp w computes output w) ----
    {
        float s = sh[lane]      * W2[lane * 4 + w]
                + sh[lane + 32] * W2[(lane + 32) * 4 + w];
        #pragma unroll
        for (int off = 16; off > 0; off >>= 1)
            s += __shfl_xor_sync(0xFFFFFFFFu, s, off);
        if (lane == 0) {
            s += b2[w];
            se[w] = sigmoidf_dev(s) * (Ymax[w] - Ymin[w]) + Ymin[w];
        }
    }
    __syncthreads();

    // ---- Per-thread parameter selection (4 consecutive c columns) ----
    int4 mk = mask4[m * C4 + t];
    int mkv[4] = {mk.x, mk.y, mk.z, mk.w};
    float e0[4], e1[4], e2[4], e3[4];
    #pragma unroll
    for (int j = 0; j < 4; j++) {
        if (mkv[j] == 0) {
            e0[j] = se[0]; e1[j] = se[1]; e2[j] = se[2]; e3[j] = se[3];
        } else {
            const float* p = &c_fault[mkv[j] - 1][0];
            e0[j] = p[0];  e1[j] = p[1];  e2[j] = p[2];  e3[j] = p[3];
        }
    }

    // ---- Main streaming loop ----
    int base = ((m * N_DIM + n) * B_DIM + chunk * BCHUNK) * C4 + t;
    #pragma unroll 4
    for (int b = 0; b < BCHUNK; b++) {
        int idx = base + b * C4;
        float4 v = __ldcs(&z[idx]);
        float4 r;
        r.x = fmaf(e1[0], fast_tanh((v.x - e2[0]) * e3[0]), e0[0]);
        r.y = fmaf(e1[1], fast_tanh((v.y - e2[1]) * e3[1]), e0[1]);
        r.z = fmaf(e1[2], fast_tanh((v.z - e2[2]) * e3[2]), e0[2]);
        r.w = fmaf(e1[3], fast_tanh((v.w - e2[3]) * e3[3]), e0[3]);
        __stcs(&out[idx], r);
    }
}

// ---------------------------------------------------------------------------
extern "C" void kernel_launch(void* const* d_in, const int* in_sizes, int n_in,
                              void* d_out, int out_size) {
    const float* z     = (const float*)d_in[0];
    const float* rt    = (const float*)d_in[1];
    const float* noise = (const float*)d_in[2];
    const float* Xmax  = (const float*)d_in[3];
    const float* Xmin  = (const float*)d_in[4];
    const float* Ymax  = (const float*)d_in[5];
    const float* Ymin  = (const float*)d_in[6];
    const float* W1    = (const float*)d_in[7];
    const float* b1    = (const float*)d_in[8];
    const float* W2    = (const float*)d_in[9];
    const float* b2    = (const float*)d_in[10];
    const int*   mask  = (const int*)  d_in[11];

    int nblocks = (B_DIM / BCHUNK) * M_DIM * N_DIM;   // 2048
    fused_tanhrt_kernel<<<nblocks, 128>>>(
        (const float4*)z, (const int4*)mask, (float4*)d_out,
        rt, noise, Xmax, Xmin, Ymax, Ymin, W1, b1, W2, b2);
}